// round 2
// baseline (speedup 1.0000x reference)
#include <cuda_runtime.h>
#include <cuda_bf16.h>
#include <math.h>

// Problem constants
#define BB   32
#define TT   4096
#define DZC  128
#define NDC  32
#define DHC  128
#define GG   384            // 3*DZ
#define IND  192            // 2*ND + DH

// ---------------- scratch (no cudaMalloc allowed) ----------------
// +2*GG pad: scan prefetches 2 steps ahead
__device__ float g_gi[(size_t)BB * TT * GG + 2 * GG];

// ---------------- packed fp32x2 helpers (sm_100+) ----------------
__device__ __forceinline__ void fma2(unsigned long long& d,
                                     unsigned long long a,
                                     unsigned long long b) {
    asm("fma.rn.f32x2 %0, %1, %2, %0;" : "+l"(d) : "l"(a), "l"(b));
}
__device__ __forceinline__ void add2(unsigned long long& d, unsigned long long a) {
    asm("add.rn.f32x2 %0, %0, %1;" : "+l"(d) : "l"(a));
}
__device__ __forceinline__ unsigned long long dup2(float a) {
    unsigned long long r;
    asm("mov.b64 %0, {%1, %1};" : "=l"(r) : "f"(a));
    return r;
}
__device__ __forceinline__ void unpk(unsigned long long v, float& x, float& y) {
    asm("mov.b64 {%0, %1}, %2;" : "=f"(x), "=f"(y) : "l"(v));
}
__device__ __forceinline__ float ex2f_(float x) {
    float y; asm("ex2.approx.f32 %0, %1;" : "=f"(y) : "f"(x)); return y;
}
__device__ __forceinline__ float rcpf_(float x) {
    float y; asm("rcp.approx.f32 %0, %1;" : "=f"(y) : "f"(x)); return y;
}
__device__ __forceinline__ float sigmoidf_(float x) {
    float e = ex2f_(-1.4426950408889634f * x);
    return rcpf_(1.0f + e);
}
__device__ __forceinline__ float tanhf_(float x) {
    float xc = fminf(fmaxf(x, -20.0f), 20.0f);
    float e = ex2f_(-2.8853900817779268f * xc);   // exp(-2x)
    return (1.0f - e) * rcpf_(1.0f + e);
}

// =====================================================================
// Kernel 1: gi_all[bt][g] = sum_k x[bt][k] * W_ih[g][k] + b_ih[g]
// x = concat(Y[32], M[32], H[128]) along k. 128x128 tile, BK=16, f32x2.
// =====================================================================
#define Bb 128
#define BN 128
#define BK 16

__global__ __launch_bounds__(256) void gi_gemm_kernel(
    const float* __restrict__ Y, const float* __restrict__ M,
    const float* __restrict__ H, const float* __restrict__ W,
    const float* __restrict__ bias, float* __restrict__ gi)
{
    __shared__ __align__(16) float As[2][BK][Bb];
    __shared__ __align__(16) float Bs[2][BK][BN];

    const int tid = threadIdx.x;
    const int bt0 = blockIdx.x * Bb;
    const int g0  = blockIdx.y * BN;
    const int tx = tid & 15;      // n-dim
    const int ty = tid >> 4;      // m-dim

    unsigned long long acc[8][4];
    #pragma unroll
    for (int i = 0; i < 8; i++)
        #pragma unroll
        for (int j = 0; j < 4; j++) acc[i][j] = 0ull;

    auto loadA = [&](int stage, int kc) {
        #pragma unroll
        for (int i = 0; i < 2; i++) {
            int e  = tid + 256 * i;
            int m  = e & 127;
            int k4 = e >> 7;                  // 0..3
            int kk = kc * BK + k4 * 4;        // global k (chunk is in one source)
            int bt = bt0 + m;
            float4 v;
            if (kk < 32)       v = *(const float4*)(Y + (size_t)bt * NDC + kk);
            else if (kk < 64)  v = *(const float4*)(M + (size_t)bt * NDC + (kk - 32));
            else               v = *(const float4*)(H + (size_t)bt * DHC + (kk - 64));
            As[stage][k4 * 4 + 0][m] = v.x;
            As[stage][k4 * 4 + 1][m] = v.y;
            As[stage][k4 * 4 + 2][m] = v.z;
            As[stage][k4 * 4 + 3][m] = v.w;
        }
    };
    auto loadB = [&](int stage, int kc) {
        #pragma unroll
        for (int i = 0; i < 2; i++) {
            int e  = tid + 256 * i;
            int g  = e & 127;
            int k4 = e >> 7;
            int kk = kc * BK + k4 * 4;
            float4 v = *(const float4*)(W + (size_t)(g0 + g) * IND + kk);
            Bs[stage][k4 * 4 + 0][g] = v.x;
            Bs[stage][k4 * 4 + 1][g] = v.y;
            Bs[stage][k4 * 4 + 2][g] = v.z;
            Bs[stage][k4 * 4 + 3][g] = v.w;
        }
    };

    loadA(0, 0); loadB(0, 0);
    __syncthreads();

    const int NKC = IND / BK;   // 12
    for (int kc = 0; kc < NKC; kc++) {
        int cur = kc & 1, nxt = cur ^ 1;
        if (kc + 1 < NKC) { loadA(nxt, kc + 1); loadB(nxt, kc + 1); }
        #pragma unroll
        for (int k = 0; k < BK; k++) {
            float a[8];
            *(float4*)&a[0] = *(const float4*)&As[cur][k][ty * 8];
            *(float4*)&a[4] = *(const float4*)&As[cur][k][ty * 8 + 4];
            unsigned long long b[4];
            {
                ulonglong2 b0 = *(const ulonglong2*)&Bs[cur][k][tx * 8];
                ulonglong2 b1 = *(const ulonglong2*)&Bs[cur][k][tx * 8 + 4];
                b[0] = b0.x; b[1] = b0.y; b[2] = b1.x; b[3] = b1.y;
            }
            #pragma unroll
            for (int i = 0; i < 8; i++) {
                unsigned long long ad = dup2(a[i]);
                fma2(acc[i][0], ad, b[0]);
                fma2(acc[i][1], ad, b[1]);
                fma2(acc[i][2], ad, b[2]);
                fma2(acc[i][3], ad, b[3]);
            }
        }
        __syncthreads();
    }

    float bia[8];
    *(float4*)&bia[0] = *(const float4*)(bias + g0 + tx * 8);
    *(float4*)&bia[4] = *(const float4*)(bias + g0 + tx * 8 + 4);

    #pragma unroll
    for (int i = 0; i < 8; i++) {
        float c[8];
        unpk(acc[i][0], c[0], c[1]);
        unpk(acc[i][1], c[2], c[3]);
        unpk(acc[i][2], c[4], c[5]);
        unpk(acc[i][3], c[6], c[7]);
        #pragma unroll
        for (int j = 0; j < 8; j++) c[j] += bia[j];
        int bt = bt0 + ty * 8 + i;
        float* out = gi + (size_t)bt * GG + g0 + tx * 8;
        *(float4*)(out)     = *(float4*)&c[0];
        *(float4*)(out + 4) = *(float4*)&c[4];
    }
}

// =====================================================================
// Kernel 2: sequential GRU scan, SYMMETRIC layout.
// One CTA per batch, 384 threads. Thread tid owns gate row tid
// (grp = tid>>7: 0=r,1=u,2=n rows; j = tid&127) AND redundantly tracks
// the full state z_j so the epilogue is computed by ALL threads
// (no idle tail between barriers). Gates exchanged via one float4.
// =====================================================================
__global__ __launch_bounds__(384, 1) void gru_scan_kernel(
    const float* __restrict__ z0, const float* __restrict__ t_dyn,
    const int* __restrict__ dyn_lens,
    const float* __restrict__ W_hh, const float* __restrict__ b_hh,
    const float* __restrict__ log_gamma,
    float* __restrict__ z_final, float* __restrict__ Z_traj)
{
    __shared__ __align__(16) float ts[TT];        // 16 KB timestamps
    __shared__ __align__(16) float zbuf[DZC];     // broadcast z_d
    __shared__ __align__(16) float gbuf[DZC * 4]; // interleaved {r,u,hn,pad}

    const int b   = blockIdx.x;
    const int tid = threadIdx.x;
    const int j   = tid & 127;
    const int grp = tid >> 7;     // 0=r, 1=u, 2=n

    for (int i = tid; i < TT; i += 384) ts[i] = t_dyn[(size_t)b * TT + i];

    // W_hh row -> registers as f32x2 pairs (64 u64 = 128 regs)
    unsigned long long Wp[64];
    {
        const ulonglong2* wr = (const ulonglong2*)(W_hh + (size_t)tid * DZC);
        #pragma unroll
        for (int i = 0; i < 32; i++) {
            ulonglong2 v = wr[i];
            Wp[2 * i]     = v.x;
            Wp[2 * i + 1] = v.y;
        }
    }
    const float bh  = b_hh[tid];
    const int   len = dyn_lens[b];

    // state (redundant across the 3 groups)
    float lg  = log_gamma[j];
    float sp  = (lg > 20.0f) ? lg : log1pf(expf(lg));  // softplus
    const float gje = -1.4426950408889634f * sp;       // pre-scaled for ex2
    float zj  = z0[(size_t)b * DZC + j];

    __syncthreads();
    float tprev = ts[0];

    // gi pointers: own gate row + n-slice for dim j; distance-2 prefetch
    const float* p_gi  = g_gi + (size_t)b * TT * GG + tid;
    const float* p_gin = g_gi + (size_t)b * TT * GG + 256 + j;
    float gi0 = p_gi[0],  gi1 = p_gi[GG];
    float gn0 = p_gin[0], gn1 = p_gin[GG];
    p_gi  += 2 * GG;
    p_gin += 2 * GG;

    float* zp = Z_traj + (size_t)b * TT * DZC + j;   // grp==2 stores

    for (int t = 0; t < TT; t++) {
        // prefetch t+2 (pad region covers the overrun at the tail)
        float gi2 = __ldg(p_gi);
        float gn2 = __ldg(p_gin);
        p_gi  += GG;
        p_gin += GG;

        // decay (all threads, registers only)
        float tk  = ts[t];
        float dt  = fmaxf(tk - tprev, 0.0f);
        tprev = tk;
        float ed  = ex2f_(gje * dt);
        float zdj = zj * ed;
        if (grp == 0) zbuf[j] = zdj;
        __syncthreads();   // A: zbuf ready (gbuf reads of t-1 done before prev B)

        // gh[row] = W_hh[row,:] . z_d : 32 LDS.128 + 64 FFMA2
        unsigned long long a0 = 0ull, a1 = 0ull, a2 = 0ull, a3 = 0ull;
        const ulonglong2* zb = (const ulonglong2*)zbuf;
        #pragma unroll
        for (int i = 0; i < 16; i++) {
            ulonglong2 v0 = zb[2 * i];
            ulonglong2 v1 = zb[2 * i + 1];
            fma2(a0, Wp[4 * i + 0], v0.x);
            fma2(a1, Wp[4 * i + 1], v0.y);
            fma2(a2, Wp[4 * i + 2], v1.x);
            fma2(a3, Wp[4 * i + 3], v1.y);
        }
        add2(a0, a1);
        add2(a2, a3);
        add2(a0, a2);
        float x0, x1;
        unpk(a0, x0, x1);
        float gh = x0 + x1 + bh;

        float gval = (grp < 2) ? sigmoidf_(gi0 + gh) : gh;
        gbuf[j * 4 + grp] = gval;
        __syncthreads();   // B: gates ready

        // epilogue (ALL threads, redundant per dim)
        float4 g4 = *(const float4*)&gbuf[j * 4];
        float nn   = tanhf_(gn0 + g4.x * g4.z);
        float znew = nn + g4.y * (zdj - nn);   // (1-u)n + u*zd
        zj = (t < len) ? znew : zdj;
        if (grp == 2) *zp = zj;
        zp += DZC;

        gi0 = gi1; gi1 = gi2;
        gn0 = gn1; gn1 = gn2;
    }

    if (grp == 2) z_final[(size_t)b * DZC + j] = zj;
}

// =====================================================================
// launch
// =====================================================================
extern "C" void kernel_launch(void* const* d_in, const int* in_sizes, int n_in,
                              void* d_out, int out_size)
{
    const float* z0        = (const float*)d_in[0];
    const float* t_dyn     = (const float*)d_in[1];
    const float* Y         = (const float*)d_in[2];
    const float* M         = (const float*)d_in[3];
    const int*   dyn_lens  = (const int*)  d_in[4];
    const float* H         = (const float*)d_in[5];
    const float* W_ih      = (const float*)d_in[6];
    const float* b_ih      = (const float*)d_in[7];
    const float* W_hh      = (const float*)d_in[8];
    const float* b_hh      = (const float*)d_in[9];
    const float* log_gamma = (const float*)d_in[10];

    float* out     = (float*)d_out;
    float* z_final = out;                       // (B, DZ)
    float* Z_traj  = out + (size_t)BB * DZC;    // (B, T, DZ)

    float* gi = nullptr;
    cudaGetSymbolAddress((void**)&gi, g_gi);

    dim3 ggrid((BB * TT) / Bb, GG / BN);        // (1024, 3)
    gi_gemm_kernel<<<ggrid, 256>>>(Y, M, H, W_ih, b_ih, gi);

    gru_scan_kernel<<<BB, 384>>>(z0, t_dyn, dyn_lens, W_hh, b_hh, log_gamma,
                                 z_final, Z_traj);
}

// round 4
// speedup vs baseline: 1.2418x; 1.2418x over previous
#include <cuda_runtime.h>
#include <cuda_bf16.h>
#include <math.h>

// Problem constants
#define BB   32
#define TT   4096
#define DZC  128
#define NDC  32
#define DHC  128
#define GG   384            // 3*DZ
#define IND  192            // 2*ND + DH

// ---------------- scratch (no cudaMalloc allowed) ----------------
// +2*GG pad: scan prefetches 2 steps ahead
__device__ float g_gi[(size_t)BB * TT * GG + 2 * GG];

// ---------------- packed fp32x2 helpers (sm_100+) ----------------
__device__ __forceinline__ void fma2(unsigned long long& d,
                                     unsigned long long a,
                                     unsigned long long b) {
    asm("fma.rn.f32x2 %0, %1, %2, %0;" : "+l"(d) : "l"(a), "l"(b));
}
__device__ __forceinline__ void add2(unsigned long long& d, unsigned long long a) {
    asm("add.rn.f32x2 %0, %0, %1;" : "+l"(d) : "l"(a));
}
__device__ __forceinline__ unsigned long long dup2(float a) {
    unsigned long long r;
    asm("mov.b64 %0, {%1, %1};" : "=l"(r) : "f"(a));
    return r;
}
__device__ __forceinline__ void unpk(unsigned long long v, float& x, float& y) {
    asm("mov.b64 {%0, %1}, %2;" : "=f"(x), "=f"(y) : "l"(v));
}
__device__ __forceinline__ float ex2f_(float x) {
    float y; asm("ex2.approx.f32 %0, %1;" : "=f"(y) : "f"(x)); return y;
}
__device__ __forceinline__ float rcpf_(float x) {
    float y; asm("rcp.approx.f32 %0, %1;" : "=f"(y) : "f"(x)); return y;
}
__device__ __forceinline__ float sigmoidf_(float x) {
    float e = ex2f_(-1.4426950408889634f * x);
    return rcpf_(1.0f + e);
}
__device__ __forceinline__ float tanhf_(float x) {
    float xc = fminf(fmaxf(x, -20.0f), 20.0f);
    float e = ex2f_(-2.8853900817779268f * xc);   // exp(-2x)
    return (1.0f - e) * rcpf_(1.0f + e);
}

// =====================================================================
// Kernel 1: gi_all[bt][g] = sum_k x[bt][k] * W_ih[g][k] + b_ih[g]
// (unchanged — scan change isolated)
// =====================================================================
#define Bb 128
#define BN 128
#define BK 16

__global__ __launch_bounds__(256) void gi_gemm_kernel(
    const float* __restrict__ Y, const float* __restrict__ M,
    const float* __restrict__ H, const float* __restrict__ W,
    const float* __restrict__ bias, float* __restrict__ gi)
{
    __shared__ __align__(16) float As[2][BK][Bb];
    __shared__ __align__(16) float Bs[2][BK][BN];

    const int tid = threadIdx.x;
    const int bt0 = blockIdx.x * Bb;
    const int g0  = blockIdx.y * BN;
    const int tx = tid & 15;      // n-dim
    const int ty = tid >> 4;      // m-dim

    unsigned long long acc[8][4];
    #pragma unroll
    for (int i = 0; i < 8; i++)
        #pragma unroll
        for (int j = 0; j < 4; j++) acc[i][j] = 0ull;

    auto loadA = [&](int stage, int kc) {
        #pragma unroll
        for (int i = 0; i < 2; i++) {
            int e  = tid + 256 * i;
            int m  = e & 127;
            int k4 = e >> 7;
            int kk = kc * BK + k4 * 4;
            int bt = bt0 + m;
            float4 v;
            if (kk < 32)       v = *(const float4*)(Y + (size_t)bt * NDC + kk);
            else if (kk < 64)  v = *(const float4*)(M + (size_t)bt * NDC + (kk - 32));
            else               v = *(const float4*)(H + (size_t)bt * DHC + (kk - 64));
            As[stage][k4 * 4 + 0][m] = v.x;
            As[stage][k4 * 4 + 1][m] = v.y;
            As[stage][k4 * 4 + 2][m] = v.z;
            As[stage][k4 * 4 + 3][m] = v.w;
        }
    };
    auto loadB = [&](int stage, int kc) {
        #pragma unroll
        for (int i = 0; i < 2; i++) {
            int e  = tid + 256 * i;
            int g  = e & 127;
            int k4 = e >> 7;
            int kk = kc * BK + k4 * 4;
            float4 v = *(const float4*)(W + (size_t)(g0 + g) * IND + kk);
            Bs[stage][k4 * 4 + 0][g] = v.x;
            Bs[stage][k4 * 4 + 1][g] = v.y;
            Bs[stage][k4 * 4 + 2][g] = v.z;
            Bs[stage][k4 * 4 + 3][g] = v.w;
        }
    };

    loadA(0, 0); loadB(0, 0);
    __syncthreads();

    const int NKC = IND / BK;   // 12
    for (int kc = 0; kc < NKC; kc++) {
        int cur = kc & 1, nxt = cur ^ 1;
        if (kc + 1 < NKC) { loadA(nxt, kc + 1); loadB(nxt, kc + 1); }
        #pragma unroll
        for (int k = 0; k < BK; k++) {
            float a[8];
            *(float4*)&a[0] = *(const float4*)&As[cur][k][ty * 8];
            *(float4*)&a[4] = *(const float4*)&As[cur][k][ty * 8 + 4];
            unsigned long long b[4];
            {
                ulonglong2 b0 = *(const ulonglong2*)&Bs[cur][k][tx * 8];
                ulonglong2 b1 = *(const ulonglong2*)&Bs[cur][k][tx * 8 + 4];
                b[0] = b0.x; b[1] = b0.y; b[2] = b1.x; b[3] = b1.y;
            }
            #pragma unroll
            for (int i = 0; i < 8; i++) {
                unsigned long long ad = dup2(a[i]);
                fma2(acc[i][0], ad, b[0]);
                fma2(acc[i][1], ad, b[1]);
                fma2(acc[i][2], ad, b[2]);
                fma2(acc[i][3], ad, b[3]);
            }
        }
        __syncthreads();
    }

    float bia[8];
    *(float4*)&bia[0] = *(const float4*)(bias + g0 + tx * 8);
    *(float4*)&bia[4] = *(const float4*)(bias + g0 + tx * 8 + 4);

    #pragma unroll
    for (int i = 0; i < 8; i++) {
        float c[8];
        unpk(acc[i][0], c[0], c[1]);
        unpk(acc[i][1], c[2], c[3]);
        unpk(acc[i][2], c[4], c[5]);
        unpk(acc[i][3], c[6], c[7]);
        #pragma unroll
        for (int j = 0; j < 8; j++) c[j] += bia[j];
        int bt = bt0 + ty * 8 + i;
        float* out = gi + (size_t)bt * GG + g0 + tx * 8;
        *(float4*)(out)     = *(float4*)&c[0];
        *(float4*)(out + 4) = *(float4*)&c[4];
    }
}

// =====================================================================
// Kernel 2: GRU scan. 256 threads, one barrier per step, DOUBLE-BUFFERED
// z_d exchange (race-free with a single barrier).
// tid -> (j = tid>>1, q = tid&1). Thread (j,q) holds K-half [64q,64q+64)
// of W_hh rows {j, 128+j, 256+j} in registers (96 u64 = 192 regs).
// Partials reduced with ONE shfl.xor(1); gates+epilogue thread-local.
// =====================================================================
__global__ __launch_bounds__(256, 1) void gru_scan_kernel(
    const float* __restrict__ z0, const float* __restrict__ t_dyn,
    const int* __restrict__ dyn_lens,
    const float* __restrict__ W_hh, const float* __restrict__ b_hh,
    const float* __restrict__ log_gamma,
    float* __restrict__ z_final, float* __restrict__ Z_traj)
{
    __shared__ __align__(16) float dtbuf[TT + 4];   // dt per step (+pad)
    __shared__ __align__(16) float zbA[DZC];        // z_d double buffer
    __shared__ __align__(16) float zbB[DZC];

    const int b   = blockIdx.x;
    const int tid = threadIdx.x;
    const int j   = tid >> 1;     // state dim 0..127
    const int q   = tid & 1;      // K-half 0..1

    // ---- dtbuf: dt[t] = max(ts[t]-ts[t-1],0), dt[0]=0, dt[TT]=0 ----
    {
        const float* tp = t_dyn + (size_t)b * TT;
        for (int i = tid; i < TT; i += 256) {
            float cur = __ldg(tp + i);
            float prv = (i > 0) ? __ldg(tp + i - 1) : cur;
            dtbuf[i] = fmaxf(cur - prv, 0.0f);
        }
        if (tid == 0) dtbuf[TT] = 0.0f;
    }

    // ---- weights: rows {j, 128+j, 256+j}, K half [64q, 64q+64) ----
    unsigned long long Wr[32], Wu[32], Wn[32];
    {
        const ulonglong2* wr = (const ulonglong2*)(W_hh + (size_t)j * DZC + 64 * q);
        const ulonglong2* wu = (const ulonglong2*)(W_hh + (size_t)(128 + j) * DZC + 64 * q);
        const ulonglong2* wn = (const ulonglong2*)(W_hh + (size_t)(256 + j) * DZC + 64 * q);
        #pragma unroll
        for (int i = 0; i < 16; i++) {
            ulonglong2 a = wr[i]; Wr[2*i] = a.x; Wr[2*i+1] = a.y;
            ulonglong2 c = wu[i]; Wu[2*i] = c.x; Wu[2*i+1] = c.y;
            ulonglong2 d = wn[i]; Wn[2*i] = d.x; Wn[2*i+1] = d.y;
        }
    }
    // bias: inject each exactly once pre-reduce.
    // q0 injects bh_r into Sr and bh_n into Sn; q1 injects bh_u into Su.
    const float bh_own = (q == 0) ? b_hh[j] : b_hh[128 + j];
    const float bh_n   = (q == 0) ? b_hh[256 + j] : 0.0f;
    const int   len = dyn_lens[b];

    float lg  = log_gamma[j];
    float sp  = (lg > 20.0f) ? lg : log1pf(expf(lg));   // softplus
    const float gje = -1.4426950408889634f * sp;        // pre-scaled for ex2

    // gi streams: own gate row (q0->r, q1->u) and n row (both lanes).
    const float* pG = g_gi + (size_t)b * TT * GG + q * DZC + j;
    const float* pN = g_gi + (size_t)b * TT * GG + 2 * DZC + j;
    float gi_c = __ldg(pG), gi_1 = __ldg(pG + GG);
    float gn_c = __ldg(pN), gn_1 = __ldg(pN + GG);
    pG += 2 * GG;
    pN += 2 * GG;

    float* zp = Z_traj + (size_t)b * TT * DZC + j;   // q0 stores

    // init: z_d(0) = z0 (dt=0)
    float zdj = z0[(size_t)b * DZC + j];
    if (q == 0) zbA[j] = zdj;

    auto step = [&](int t, const float* __restrict__ zr, float* __restrict__ zw) {
        __syncthreads();   // zr(t) visible; zw free (WAR-safe: see theory)

        // off-critical-path: decay factor for t+1, gi prefetch t+2
        float edn  = ex2f_(gje * dtbuf[t + 1]);
        float gi_2 = __ldg(pG);
        float gn_2 = __ldg(pN);
        pG += GG; pN += GG;

        // dot over K-half: 16 LDS.128 (broadcast across j, 2-way across q),
        // 96 fma2 into 6 accumulators
        unsigned long long ar0 = 0, ar1 = 0, au0 = 0, au1 = 0, an0 = 0, an1 = 0;
        const ulonglong2* zc = (const ulonglong2*)(zr + 64 * q);
        #pragma unroll
        for (int i = 0; i < 16; i += 2) {
            ulonglong2 v0 = zc[i];
            ulonglong2 v1 = zc[i + 1];
            fma2(ar0, Wr[2*i],   v0.x); fma2(ar0, Wr[2*i+1], v0.y);
            fma2(au0, Wu[2*i],   v0.x); fma2(au0, Wu[2*i+1], v0.y);
            fma2(an0, Wn[2*i],   v0.x); fma2(an0, Wn[2*i+1], v0.y);
            fma2(ar1, Wr[2*i+2], v1.x); fma2(ar1, Wr[2*i+3], v1.y);
            fma2(au1, Wu[2*i+2], v1.x); fma2(au1, Wu[2*i+3], v1.y);
            fma2(an1, Wn[2*i+2], v1.x); fma2(an1, Wn[2*i+3], v1.y);
        }
        add2(ar0, ar1); add2(au0, au1); add2(an0, an1);
        float r0, r1, u0, u1, n0, n1;
        unpk(ar0, r0, r1); unpk(au0, u0, u1); unpk(an0, n0, n1);
        float Sr = r0 + r1, Su = u0 + u1, Sn = n0 + n1;

        // inject gi + bias once per gate
        if (q == 0) { Sr += gi_c + bh_own; Sn += bh_n; }
        else        { Su += gi_c + bh_own; }

        // one reduce round across the lane pair
        Sr += __shfl_xor_sync(0xffffffffu, Sr, 1);
        Su += __shfl_xor_sync(0xffffffffu, Su, 1);
        Sn += __shfl_xor_sync(0xffffffffu, Sn, 1);

        // gates + epilogue (both lanes, identical)
        float rr = sigmoidf_(Sr);
        float uu = sigmoidf_(Su);
        float nn = tanhf_(gn_c + rr * Sn);
        float znew = nn + uu * (zdj - nn);
        float zj   = (t < len) ? znew : zdj;
        if (q == 0) *zp = zj;
        zp += DZC;

        zdj = zj * edn;            // z_d for step t+1 (edn(TT-1 tail)=1)
        if (q == 0) zw[j] = zdj;

        gi_c = gi_1; gi_1 = gi_2;
        gn_c = gn_1; gn_1 = gn_2;
    };

    for (int t = 0; t < TT; t += 2) {
        step(t,     zbA, zbB);
        step(t + 1, zbB, zbA);
    }

    // dt[TT]=0 -> final edn==1 -> zdj == last zj
    if (q == 0) z_final[(size_t)b * DZC + j] = zdj;
}

// =====================================================================
// launch
// =====================================================================
extern "C" void kernel_launch(void* const* d_in, const int* in_sizes, int n_in,
                              void* d_out, int out_size)
{
    const float* z0        = (const float*)d_in[0];
    const float* t_dyn     = (const float*)d_in[1];
    const float* Y         = (const float*)d_in[2];
    const float* M         = (const float*)d_in[3];
    const int*   dyn_lens  = (const int*)  d_in[4];
    const float* H         = (const float*)d_in[5];
    const float* W_ih      = (const float*)d_in[6];
    const float* b_ih      = (const float*)d_in[7];
    const float* W_hh      = (const float*)d_in[8];
    const float* b_hh      = (const float*)d_in[9];
    const float* log_gamma = (const float*)d_in[10];

    float* out     = (float*)d_out;
    float* z_final = out;                       // (B, DZ)
    float* Z_traj  = out + (size_t)BB * DZC;    // (B, T, DZ)

    float* gi = nullptr;
    cudaGetSymbolAddress((void**)&gi, g_gi);

    dim3 ggrid((BB * TT) / Bb, GG / BN);        // (1024, 3)
    gi_gemm_kernel<<<ggrid, 256>>>(Y, M, H, W_ih, b_ih, gi);

    gru_scan_kernel<<<BB, 256>>>(z0, t_dyn, dyn_lens, W_hh, b_hh, log_gamma,
                                 z_final, Z_traj);
}